// round 1
// baseline (speedup 1.0000x reference)
#include <cuda_runtime.h>

#define BB 2
#define SEQ 2048
#define NHALF 1024
#define DIM 768
#define HEADS 12
#define HD 64
#define DFF 3072
#define COND 128
#define ADA6 (6 * DIM)

// ---------------- scratch (allocation-free: __device__ globals) ----------------
__device__ float g_ada[BB * ADA6];
__device__ float g_h[BB * SEQ * DIM];
__device__ float g_qkv[BB * SEQ * 3 * DIM];
__device__ float g_o[BB * SEQ * DIM];
__device__ float g_x1[BB * SEQ * DIM];
__device__ float g_h2[BB * SEQ * DIM];
__device__ float g_mlp[BB * SEQ * DFF];

// ---------------- 1. ada = c @ ada_w + ada_b ----------------
__global__ void ada_kernel(const float* __restrict__ c,
                           const float* __restrict__ ada_w,
                           const float* __restrict__ ada_b) {
    int j = blockIdx.x * blockDim.x + threadIdx.x;
    if (j >= BB * ADA6) return;
    int b = j / ADA6, col = j % ADA6;
    float acc = ada_b[col];
    #pragma unroll 8
    for (int k = 0; k < COND; k++)
        acc += c[b * COND + k] * ada_w[k * ADA6 + col];
    g_ada[j] = acc;
}

// ---------------- 2. LayerNorm + adaLN modulation ----------------
// dst = LN(src) * lnw * (1 + ada[scale_ofs]) + ada[shift_ofs]
__global__ void ln_mod_kernel(const float* __restrict__ src, float* __restrict__ dst,
                              const float* __restrict__ lnw,
                              int shift_ofs, int scale_ofs) {
    int row = blockIdx.x;          // 0 .. B*SEQ-1
    int b = row / SEQ;
    const float* xr = src + (size_t)row * DIM;
    float s = 0.f, s2 = 0.f;
    for (int i = threadIdx.x; i < DIM; i += blockDim.x) {
        float v = xr[i];
        s += v; s2 += v * v;
    }
    #pragma unroll
    for (int o = 16; o; o >>= 1) {
        s  += __shfl_xor_sync(0xffffffffu, s,  o);
        s2 += __shfl_xor_sync(0xffffffffu, s2, o);
    }
    __shared__ float red[64];
    int wid = threadIdx.x >> 5, lid = threadIdx.x & 31;
    if (lid == 0) { red[wid] = s; red[32 + wid] = s2; }
    __syncthreads();
    if (threadIdx.x == 0) {
        float a = 0.f, bsum = 0.f;
        int nw = blockDim.x >> 5;
        for (int w = 0; w < nw; w++) { a += red[w]; bsum += red[32 + w]; }
        red[0] = a; red[32] = bsum;
    }
    __syncthreads();
    float mu  = red[0] * (1.0f / DIM);
    float var = red[32] * (1.0f / DIM) - mu * mu;
    float inv = rsqrtf(var + 1e-5f);
    const float* ada = g_ada + b * ADA6;
    for (int i = threadIdx.x; i < DIM; i += blockDim.x) {
        float v = (xr[i] - mu) * inv * lnw[i];
        dst[(size_t)row * DIM + i] = v * (1.f + ada[scale_ofs + i]) + ada[shift_ofs + i];
    }
}

// ---------------- 3. Tiled fp32 GEMM with fused epilogues ----------------
// C[M,N] = A[M,K] @ B[K,N] ; M = B*SEQ = 4096 (all dims multiples of tile sizes)
// mode 0: none
// mode 1: C = gate[b,col] * acc + res[row,col]            (gate_ofs into g_ada)
// mode 2: C = gelu_tanh(acc + bias[col])
// mode 3: C = gate[b,col] * (acc + bias[col]) + res[row,col]
#define TBM 64
#define TBN 64
#define TBK 16
__global__ void gemm_kernel(const float* __restrict__ A, const float* __restrict__ Bm,
                            float* __restrict__ C, int N, int K, int mode,
                            const float* __restrict__ bias,
                            const float* __restrict__ res, int gate_ofs) {
    __shared__ float As[TBK][TBM];
    __shared__ float Bs[TBK][TBN];
    int m0 = blockIdx.y * TBM, n0 = blockIdx.x * TBN;
    int tid = threadIdx.x;
    int ty = tid >> 4, tx = tid & 15;
    float acc[4][4] = {};
    for (int k0 = 0; k0 < K; k0 += TBK) {
        #pragma unroll
        for (int r = 0; r < 4; r++) {
            int e = tid + r * 256;
            int m = e >> 4, k = e & 15;
            As[k][m] = A[(size_t)(m0 + m) * K + k0 + k];
        }
        #pragma unroll
        for (int r = 0; r < 4; r++) {
            int e = tid + r * 256;
            int k = e >> 6, n = e & 63;
            Bs[k][n] = Bm[(size_t)(k0 + k) * N + n0 + n];
        }
        __syncthreads();
        #pragma unroll
        for (int kk = 0; kk < TBK; kk++) {
            float4 a4 = *(const float4*)&As[kk][ty * 4];
            float4 b4 = *(const float4*)&Bs[kk][tx * 4];
            float av[4] = {a4.x, a4.y, a4.z, a4.w};
            float bv[4] = {b4.x, b4.y, b4.z, b4.w};
            #pragma unroll
            for (int i = 0; i < 4; i++)
                #pragma unroll
                for (int j = 0; j < 4; j++)
                    acc[i][j] += av[i] * bv[j];
        }
        __syncthreads();
    }
    #pragma unroll
    for (int i = 0; i < 4; i++) {
        int row = m0 + ty * 4 + i;
        int bidx = row >> 11;               // row / SEQ
        #pragma unroll
        for (int j = 0; j < 4; j++) {
            int col = n0 + tx * 4 + j;
            float v = acc[i][j];
            if (mode == 1) {
                float g = g_ada[bidx * ADA6 + gate_ofs + col];
                v = g * v + res[(size_t)row * N + col];
            } else if (mode == 2) {
                v += bias[col];
                float x3 = v * v * v;
                v = 0.5f * v * (1.f + tanhf(0.7978845608028654f * (v + 0.044715f * x3)));
            } else if (mode == 3) {
                v += bias[col];
                float g = g_ada[bidx * ADA6 + gate_ofs + col];
                v = g * v + res[(size_t)row * N + col];
            }
            C[(size_t)row * N + col] = v;
        }
    }
}

// ---------------- 4. RoPE on q, k AND v (reference ropes the whole qkv) ----------------
__global__ void rope_kernel(const float* __restrict__ cosb, const float* __restrict__ sinb) {
    int idx = blockIdx.x * blockDim.x + threadIdx.x;
    const int total = BB * SEQ * 3 * HEADS * 32;
    if (idx >= total) return;
    int d = idx & 31;
    int h = (idx >> 5) % HEADS;
    int t = (idx / (32 * HEADS)) % 3;
    int pos = (idx / (32 * HEADS * 3)) % SEQ;
    int b = idx / (32 * HEADS * 3 * SEQ);
    int ph = pos & (NHALF - 1);             // position within the half
    float c1 = cosb[ph * HD + d],      s1 = sinb[ph * HD + d];
    float c2 = cosb[ph * HD + d + 32], s2 = sinb[ph * HD + d + 32];
    float* base = g_qkv + ((size_t)(b * SEQ + pos) * 3 + t) * DIM + h * HD;
    float v1 = base[d], v2 = base[d + 32];
    base[d]      = v1 * c1 - v2 * s1;       // rotate_half: first half gets -x2
    base[d + 32] = v2 * c2 + v1 * s2;       // second half gets +x1
}

// ---------------- 5. Block-sparse attention (online softmax) ----------------
// Mask structure: query-block qb (16 rows) attends to exactly (qb&63)+1 kv blocks:
//   first half  (qb<64):  {qb} ∪ {64+bk : bk < qb}
//   second half (qb>=64): {64+bk : bk <= qb-64}
__global__ void attn_kernel() {
    int qb = blockIdx.x;    // 0..127
    int h  = blockIdx.y;    // 0..11
    int b  = blockIdx.z;    // 0..1
    __shared__ float Ks[16][64];
    __shared__ float Vs[16][64];
    int tid = threadIdx.x;              // 512 threads, 16 warps
    int w = tid >> 5, lane = tid & 31;
    int qpos = qb * 16 + w;             // each warp owns one query row
    size_t qbase = ((size_t)(b * SEQ + qpos) * 3) * DIM + h * HD;
    float qa  = g_qkv[qbase + lane];
    float qbv = g_qkv[qbase + lane + 32];
    int bl = qb & 63;
    bool second = qb >= 64;
    int niter = bl + 1;
    float m = -1e30f, l = 0.f, a0 = 0.f, a1 = 0.f;
    for (int it = 0; it < niter; it++) {
        int kb = second ? (64 + it) : (it == 0 ? qb : 64 + (it - 1));
        for (int r = tid; r < 1024; r += 512) {
            int row = r >> 6, d = r & 63;
            int kpos = kb * 16 + row;
            size_t kbase = ((size_t)(b * SEQ + kpos) * 3 + 1) * DIM + h * HD + d;
            Ks[row][d] = g_qkv[kbase];
            Vs[row][d] = g_qkv[kbase + DIM];   // t=2 is DIM further
        }
        __syncthreads();
        float sloc[16];
        #pragma unroll
        for (int j = 0; j < 16; j++) {
            float p = qa * Ks[j][lane] + qbv * Ks[j][lane + 32];
            #pragma unroll
            for (int o = 16; o; o >>= 1) p += __shfl_xor_sync(0xffffffffu, p, o);
            sloc[j] = p * 0.125f;              // 1/sqrt(64)
        }
        float bm = sloc[0];
        #pragma unroll
        for (int j = 1; j < 16; j++) bm = fmaxf(bm, sloc[j]);
        float nm = fmaxf(m, bm);
        float corr = __expf(m - nm);
        l *= corr; a0 *= corr; a1 *= corr;
        #pragma unroll
        for (int j = 0; j < 16; j++) {
            float p = __expf(sloc[j] - nm);
            l += p;
            a0 += p * Vs[j][lane];
            a1 += p * Vs[j][lane + 32];
        }
        m = nm;
        __syncthreads();
    }
    float invl = 1.f / l;
    size_t obase = (size_t)(b * SEQ + qpos) * DIM + h * HD;
    g_o[obase + lane]      = a0 * invl;
    g_o[obase + lane + 32] = a1 * invl;
}

// ---------------- launch ----------------
extern "C" void kernel_launch(void* const* d_in, const int* in_sizes, int n_in,
                              void* d_out, int out_size) {
    const float* x     = (const float*)d_in[0];
    const float* cosb  = (const float*)d_in[1];
    const float* sinb  = (const float*)d_in[2];
    const float* c     = (const float*)d_in[3];
    const float* W_qkv = (const float*)d_in[4];
    const float* W_out = (const float*)d_in[5];
    const float* ln1_w = (const float*)d_in[6];
    const float* ln2_w = (const float*)d_in[7];
    const float* w1    = (const float*)d_in[8];
    const float* b1    = (const float*)d_in[9];
    const float* w2    = (const float*)d_in[10];
    const float* b2    = (const float*)d_in[11];
    const float* ada_w = (const float*)d_in[12];
    const float* ada_b = (const float*)d_in[13];
    float* out = (float*)d_out;

    float *h, *qkv, *o, *x1, *h2, *mlp;
    cudaGetSymbolAddress((void**)&h,   g_h);
    cudaGetSymbolAddress((void**)&qkv, g_qkv);
    cudaGetSymbolAddress((void**)&o,   g_o);
    cudaGetSymbolAddress((void**)&x1,  g_x1);
    cudaGetSymbolAddress((void**)&h2,  g_h2);
    cudaGetSymbolAddress((void**)&mlp, g_mlp);

    const int M = BB * SEQ;  // 4096

    // 1. adaLN conditioning vector
    ada_kernel<<<(BB * ADA6 + 255) / 256, 256>>>(c, ada_w, ada_b);
    // 2. LN1 + modulate (shift_msa@0, scale_msa@DIM)
    ln_mod_kernel<<<M, 256>>>(x, h, ln1_w, 0, DIM);
    // 3. QKV GEMM (no epilogue)
    gemm_kernel<<<dim3(3 * DIM / TBN, M / TBM), 256>>>(h, W_qkv, qkv, 3 * DIM, DIM, 0,
                                                       nullptr, nullptr, 0);
    // 4. RoPE on q,k,v
    {
        int total = BB * SEQ * 3 * HEADS * 32;
        rope_kernel<<<(total + 255) / 256, 256>>>(cosb, sinb);
    }
    // 5. block-sparse attention
    attn_kernel<<<dim3(128, HEADS, BB), 512>>>();
    // 6. out-proj + gate_msa (ada ofs 2*DIM) + residual(x)  -> x1
    gemm_kernel<<<dim3(DIM / TBN, M / TBM), 256>>>(o, W_out, x1, DIM, DIM, 1,
                                                   nullptr, x, 2 * DIM);
    // 7. LN2 + modulate (shift_mlp@3*DIM, scale_mlp@4*DIM)
    ln_mod_kernel<<<M, 256>>>(x1, h2, ln2_w, 3 * DIM, 4 * DIM);
    // 8. MLP1 + bias + gelu(tanh)
    gemm_kernel<<<dim3(DFF / TBN, M / TBM), 256>>>(h2, w1, mlp, DFF, DIM, 2,
                                                   b1, nullptr, 0);
    // 9. MLP2 + bias + gate_mlp (ada ofs 5*DIM) + residual(x1) -> d_out
    gemm_kernel<<<dim3(DIM / TBN, M / TBM), 256>>>(mlp, w2, out, DIM, DFF, 3,
                                                   b2, x1, 5 * DIM);
}

// round 2
// speedup vs baseline: 1.9583x; 1.9583x over previous
#include <cuda_runtime.h>

#define BB 2
#define SEQ 2048
#define NHALF 1024
#define DIM 768
#define HEADS 12
#define HD 64
#define DFF 3072
#define COND 128
#define ADA6 (6 * DIM)

// ---------------- scratch (allocation-free: __device__ globals) ----------------
__device__ float g_ada[BB * ADA6];
__device__ float g_h[BB * SEQ * DIM];
__device__ float g_qkv[BB * SEQ * 3 * DIM];
__device__ float g_o[BB * SEQ * DIM];
__device__ float g_x1[BB * SEQ * DIM];
__device__ float g_h2[BB * SEQ * DIM];
__device__ float g_mlp[BB * SEQ * DFF];

// ---------------- 1. ada = c @ ada_w + ada_b ----------------
__global__ void ada_kernel(const float* __restrict__ c,
                           const float* __restrict__ ada_w,
                           const float* __restrict__ ada_b) {
    int j = blockIdx.x * blockDim.x + threadIdx.x;
    if (j >= BB * ADA6) return;
    int b = j / ADA6, col = j % ADA6;
    float acc = ada_b[col];
    #pragma unroll 8
    for (int k = 0; k < COND; k++)
        acc += c[b * COND + k] * ada_w[k * ADA6 + col];
    g_ada[j] = acc;
}

// ---------------- 2. LayerNorm + adaLN modulation ----------------
__global__ void ln_mod_kernel(const float* __restrict__ src, float* __restrict__ dst,
                              const float* __restrict__ lnw,
                              int shift_ofs, int scale_ofs) {
    int row = blockIdx.x;          // 0 .. B*SEQ-1
    int b = row / SEQ;
    const float* xr = src + (size_t)row * DIM;
    float s = 0.f, s2 = 0.f;
    for (int i = threadIdx.x; i < DIM; i += blockDim.x) {
        float v = xr[i];
        s += v; s2 += v * v;
    }
    #pragma unroll
    for (int o = 16; o; o >>= 1) {
        s  += __shfl_xor_sync(0xffffffffu, s,  o);
        s2 += __shfl_xor_sync(0xffffffffu, s2, o);
    }
    __shared__ float red[64];
    int wid = threadIdx.x >> 5, lid = threadIdx.x & 31;
    if (lid == 0) { red[wid] = s; red[32 + wid] = s2; }
    __syncthreads();
    if (threadIdx.x == 0) {
        float a = 0.f, bsum = 0.f;
        int nw = blockDim.x >> 5;
        for (int w = 0; w < nw; w++) { a += red[w]; bsum += red[32 + w]; }
        red[0] = a; red[32] = bsum;
    }
    __syncthreads();
    float mu  = red[0] * (1.0f / DIM);
    float var = red[32] * (1.0f / DIM) - mu * mu;
    float inv = rsqrtf(var + 1e-5f);
    const float* ada = g_ada + b * ADA6;
    for (int i = threadIdx.x; i < DIM; i += blockDim.x) {
        float v = (xr[i] - mu) * inv * lnw[i];
        dst[(size_t)row * DIM + i] = v * (1.f + ada[scale_ofs + i]) + ada[shift_ofs + i];
    }
}

// ---------------- 3. TF32 tensor-core GEMM (mma.sync) with fused epilogues ----------------
// C[M,N] = A[M,K] @ B[K,N], M=4096, tiles 128x128x32, 256 thr = 8 warps (4m x 2n)
// mode 0: none | 1: gate*acc+res | 2: gelu(acc+bias) | 3: gate*(acc+bias)+res
#define SSTR 136   // smem row stride (floats); 136 % 32 == 8 -> conflict-free frags

__device__ __forceinline__ unsigned f2tf(float f) {
    unsigned u;
    asm("cvt.rna.tf32.f32 %0, %1;" : "=r"(u) : "f"(f));
    return u;
}

__device__ __forceinline__ void mma_tf32(float* c, const unsigned* a, const unsigned* b) {
    asm volatile(
        "mma.sync.aligned.m16n8k8.row.col.f32.tf32.tf32.f32 "
        "{%0,%1,%2,%3}, {%4,%5,%6,%7}, {%8,%9}, {%0,%1,%2,%3};"
        : "+f"(c[0]), "+f"(c[1]), "+f"(c[2]), "+f"(c[3])
        : "r"(a[0]), "r"(a[1]), "r"(a[2]), "r"(a[3]), "r"(b[0]), "r"(b[1]));
}

__global__ void __launch_bounds__(256)
gemm_mma(const float* __restrict__ A, const float* __restrict__ Bm,
         float* __restrict__ C, int N, int K, int mode,
         const float* __restrict__ bias,
         const float* __restrict__ res, int gate_ofs) {
    __shared__ unsigned As[32 * SSTR];
    __shared__ unsigned Bs[32 * SSTR];
    int tid  = threadIdx.x;
    int lane = tid & 31, warp = tid >> 5;
    int warpm = warp >> 1, warpn = warp & 1;
    int g = lane >> 2, tg = lane & 3;
    int m0 = blockIdx.y * 128, n0 = blockIdx.x * 128;

    float acc[2][8][4] = {};
    float4 ra[4], rb[4];

    // prologue gmem load (tile k0=0)
    #pragma unroll
    for (int i = 0; i < 4; i++) {
        int e = tid + i * 256;
        int m = e >> 3, kq = (e & 7) * 4;
        ra[i] = *(const float4*)&A[(size_t)(m0 + m) * K + kq];
        int kb = e >> 5, n4 = (e & 31) * 4;
        rb[i] = *(const float4*)&Bm[(size_t)kb * N + n0 + n4];
    }

    for (int k0 = 0; k0 < K; k0 += 32) {
        // stage regs -> smem (with rna tf32 rounding)
        #pragma unroll
        for (int i = 0; i < 4; i++) {
            int e = tid + i * 256;
            int m = e >> 3, kq = (e & 7) * 4;
            float v[4] = {ra[i].x, ra[i].y, ra[i].z, ra[i].w};
            #pragma unroll
            for (int j = 0; j < 4; j++) {
                int k = kq + j;
                As[k * SSTR + (m ^ ((k >> 2) & 7))] = f2tf(v[j]);
            }
            int kb = e >> 5, n4 = (e & 31) * 4;
            uint4 p = make_uint4(f2tf(rb[i].x), f2tf(rb[i].y), f2tf(rb[i].z), f2tf(rb[i].w));
            *(uint4*)&Bs[kb * SSTR + n4] = p;
        }
        __syncthreads();
        // prefetch next gmem tile
        if (k0 + 32 < K) {
            #pragma unroll
            for (int i = 0; i < 4; i++) {
                int e = tid + i * 256;
                int m = e >> 3, kq = (e & 7) * 4;
                ra[i] = *(const float4*)&A[(size_t)(m0 + m) * K + k0 + 32 + kq];
                int kb = e >> 5, n4 = (e & 31) * 4;
                rb[i] = *(const float4*)&Bm[(size_t)(k0 + 32 + kb) * N + n0 + n4];
            }
        }
        // compute 128x128x32
        #pragma unroll
        for (int ks = 0; ks < 4; ks++) {
            int kk = ks * 8 + tg;
            int sw0 = (kk >> 2) & 7, sw1 = ((kk + 4) >> 2) & 7;
            unsigned a[2][4], b[8][2];
            #pragma unroll
            for (int mt = 0; mt < 2; mt++) {
                int mr = warpm * 32 + mt * 16 + g;
                a[mt][0] = As[kk * SSTR + (mr ^ sw0)];
                a[mt][1] = As[kk * SSTR + ((mr + 8) ^ sw0)];
                a[mt][2] = As[(kk + 4) * SSTR + (mr ^ sw1)];
                a[mt][3] = As[(kk + 4) * SSTR + ((mr + 8) ^ sw1)];
            }
            #pragma unroll
            for (int nt = 0; nt < 8; nt++) {
                int nc = warpn * 64 + nt * 8 + g;
                b[nt][0] = Bs[kk * SSTR + nc];
                b[nt][1] = Bs[(kk + 4) * SSTR + nc];
            }
            #pragma unroll
            for (int mt = 0; mt < 2; mt++)
                #pragma unroll
                for (int nt = 0; nt < 8; nt++)
                    mma_tf32(acc[mt][nt], a[mt], b[nt]);
        }
        __syncthreads();
    }

    // epilogue
    #pragma unroll
    for (int mt = 0; mt < 2; mt++) {
        #pragma unroll
        for (int i = 0; i < 2; i++) {
            int row = m0 + warpm * 32 + mt * 16 + g + i * 8;
            int bidx = row >> 11;
            #pragma unroll
            for (int nt = 0; nt < 8; nt++) {
                int col = n0 + warpn * 64 + nt * 8 + 2 * tg;
                float v0 = acc[mt][nt][i * 2 + 0];
                float v1 = acc[mt][nt][i * 2 + 1];
                if (mode == 1) {
                    float g0 = g_ada[bidx * ADA6 + gate_ofs + col];
                    float g1 = g_ada[bidx * ADA6 + gate_ofs + col + 1];
                    v0 = g0 * v0 + res[(size_t)row * N + col];
                    v1 = g1 * v1 + res[(size_t)row * N + col + 1];
                } else if (mode == 2) {
                    v0 += bias[col]; v1 += bias[col + 1];
                    float t0 = v0 * v0 * v0, t1 = v1 * v1 * v1;
                    v0 = 0.5f * v0 * (1.f + tanhf(0.7978845608028654f * (v0 + 0.044715f * t0)));
                    v1 = 0.5f * v1 * (1.f + tanhf(0.7978845608028654f * (v1 + 0.044715f * t1)));
                } else if (mode == 3) {
                    v0 += bias[col]; v1 += bias[col + 1];
                    float g0 = g_ada[bidx * ADA6 + gate_ofs + col];
                    float g1 = g_ada[bidx * ADA6 + gate_ofs + col + 1];
                    v0 = g0 * v0 + res[(size_t)row * N + col];
                    v1 = g1 * v1 + res[(size_t)row * N + col + 1];
                }
                *(float2*)&C[(size_t)row * N + col] = make_float2(v0, v1);
            }
        }
    }
}

// ---------------- 4. RoPE on q, k AND v ----------------
__global__ void rope_kernel(const float* __restrict__ cosb, const float* __restrict__ sinb) {
    int idx = blockIdx.x * blockDim.x + threadIdx.x;
    const int total = BB * SEQ * 3 * HEADS * 32;
    if (idx >= total) return;
    int d = idx & 31;
    int h = (idx >> 5) % HEADS;
    int t = (idx / (32 * HEADS)) % 3;
    int pos = (idx / (32 * HEADS * 3)) % SEQ;
    int b = idx / (32 * HEADS * 3 * SEQ);
    int ph = pos & (NHALF - 1);
    float c1 = cosb[ph * HD + d],      s1 = sinb[ph * HD + d];
    float c2 = cosb[ph * HD + d + 32], s2 = sinb[ph * HD + d + 32];
    float* base = g_qkv + ((size_t)(b * SEQ + pos) * 3 + t) * DIM + h * HD;
    float v1 = base[d], v2 = base[d + 32];
    base[d]      = v1 * c1 - v2 * s1;
    base[d + 32] = v2 * c2 + v1 * s2;
}

// ---------------- 5. Block-sparse attention (online softmax) ----------------
__global__ void attn_kernel() {
    int qb = blockIdx.x;    // 0..127
    int h  = blockIdx.y;    // 0..11
    int b  = blockIdx.z;    // 0..1
    __shared__ float Ks[16][64];
    __shared__ float Vs[16][64];
    int tid = threadIdx.x;              // 512 threads, 16 warps
    int w = tid >> 5, lane = tid & 31;
    int qpos = qb * 16 + w;
    size_t qbase = ((size_t)(b * SEQ + qpos) * 3) * DIM + h * HD;
    float qa  = g_qkv[qbase + lane];
    float qbv = g_qkv[qbase + lane + 32];
    int bl = qb & 63;
    bool second = qb >= 64;
    int niter = bl + 1;
    float m = -1e30f, l = 0.f, a0 = 0.f, a1 = 0.f;
    for (int it = 0; it < niter; it++) {
        int kb = second ? (64 + it) : (it == 0 ? qb : 64 + (it - 1));
        for (int r = tid; r < 1024; r += 512) {
            int row = r >> 6, d = r & 63;
            int kpos = kb * 16 + row;
            size_t kbase = ((size_t)(b * SEQ + kpos) * 3 + 1) * DIM + h * HD + d;
            Ks[row][d] = g_qkv[kbase];
            Vs[row][d] = g_qkv[kbase + DIM];
        }
        __syncthreads();
        float sloc[16];
        #pragma unroll
        for (int j = 0; j < 16; j++) {
            float p = qa * Ks[j][lane] + qbv * Ks[j][lane + 32];
            #pragma unroll
            for (int o = 16; o; o >>= 1) p += __shfl_xor_sync(0xffffffffu, p, o);
            sloc[j] = p * 0.125f;
        }
        float bm = sloc[0];
        #pragma unroll
        for (int j = 1; j < 16; j++) bm = fmaxf(bm, sloc[j]);
        float nm = fmaxf(m, bm);
        float corr = __expf(m - nm);
        l *= corr; a0 *= corr; a1 *= corr;
        #pragma unroll
        for (int j = 0; j < 16; j++) {
            float p = __expf(sloc[j] - nm);
            l += p;
            a0 += p * Vs[j][lane];
            a1 += p * Vs[j][lane + 32];
        }
        m = nm;
        __syncthreads();
    }
    float invl = 1.f / l;
    size_t obase = (size_t)(b * SEQ + qpos) * DIM + h * HD;
    g_o[obase + lane]      = a0 * invl;
    g_o[obase + lane + 32] = a1 * invl;
}

// ---------------- launch ----------------
extern "C" void kernel_launch(void* const* d_in, const int* in_sizes, int n_in,
                              void* d_out, int out_size) {
    const float* x     = (const float*)d_in[0];
    const float* cosb  = (const float*)d_in[1];
    const float* sinb  = (const float*)d_in[2];
    const float* c     = (const float*)d_in[3];
    const float* W_qkv = (const float*)d_in[4];
    const float* W_out = (const float*)d_in[5];
    const float* ln1_w = (const float*)d_in[6];
    const float* ln2_w = (const float*)d_in[7];
    const float* w1    = (const float*)d_in[8];
    const float* b1    = (const float*)d_in[9];
    const float* w2    = (const float*)d_in[10];
    const float* b2    = (const float*)d_in[11];
    const float* ada_w = (const float*)d_in[12];
    const float* ada_b = (const float*)d_in[13];
    float* out = (float*)d_out;

    float *h, *qkv, *o, *x1, *h2, *mlp;
    cudaGetSymbolAddress((void**)&h,   g_h);
    cudaGetSymbolAddress((void**)&qkv, g_qkv);
    cudaGetSymbolAddress((void**)&o,   g_o);
    cudaGetSymbolAddress((void**)&x1,  g_x1);
    cudaGetSymbolAddress((void**)&h2,  g_h2);
    cudaGetSymbolAddress((void**)&mlp, g_mlp);

    const int M = BB * SEQ;  // 4096

    ada_kernel<<<(BB * ADA6 + 255) / 256, 256>>>(c, ada_w, ada_b);
    ln_mod_kernel<<<M, 256>>>(x, h, ln1_w, 0, DIM);
    // QKV GEMM
    gemm_mma<<<dim3(3 * DIM / 128, M / 128), 256>>>(h, W_qkv, qkv, 3 * DIM, DIM, 0,
                                                    nullptr, nullptr, 0);
    {
        int total = BB * SEQ * 3 * HEADS * 32;
        rope_kernel<<<(total + 255) / 256, 256>>>(cosb, sinb);
    }
    attn_kernel<<<dim3(128, HEADS, BB), 512>>>();
    // out-proj + gate_msa + residual(x)
    gemm_mma<<<dim3(DIM / 128, M / 128), 256>>>(o, W_out, x1, DIM, DIM, 1,
                                                nullptr, x, 2 * DIM);
    ln_mod_kernel<<<M, 256>>>(x1, h2, ln2_w, 3 * DIM, 4 * DIM);
    // MLP1 + bias + gelu
    gemm_mma<<<dim3(DFF / 128, M / 128), 256>>>(h2, w1, mlp, DFF, DIM, 2,
                                                b1, nullptr, 0);
    // MLP2 + bias + gate_mlp + residual(x1)
    gemm_mma<<<dim3(DIM / 128, M / 128), 256>>>(mlp, w2, out, DIM, DFF, 3,
                                                b2, x1, 5 * DIM);
}

// round 3
// speedup vs baseline: 2.5562x; 1.3053x over previous
#include <cuda_runtime.h>
#include <cuda_bf16.h>

#define BB 2
#define SEQ 2048
#define NHALF 1024
#define DIM 768
#define HEADS 12
#define HD 64
#define DFF 3072
#define COND 128
#define ADA6 (6 * DIM)

typedef __nv_bfloat16 bf16;

// ---------------- scratch ----------------
__device__ float g_ada[BB * ADA6];
__device__ bf16  g_h  [BB * SEQ * DIM];
__device__ float g_qkv[BB * SEQ * 3 * DIM];
__device__ bf16  g_o  [BB * SEQ * DIM];
__device__ float g_x1 [BB * SEQ * DIM];
__device__ bf16  g_h2 [BB * SEQ * DIM];
__device__ bf16  g_mlp[BB * SEQ * DFF];
// bf16 weight copies
__device__ bf16 g_wq[DIM * 3 * DIM];
__device__ bf16 g_wo[DIM * DIM];
__device__ bf16 g_w1[DIM * DFF];
__device__ bf16 g_w2[DFF * DIM];

// ---------------- weight conversion ----------------
__global__ void cvt_kernel(const float* __restrict__ src, bf16* __restrict__ dst, int n) {
    int i = blockIdx.x * blockDim.x + threadIdx.x;
    int stride = gridDim.x * blockDim.x;
    for (; i < n; i += stride) dst[i] = __float2bfloat16(src[i]);
}

// ---------------- ada = c @ ada_w + ada_b ----------------
__global__ void ada_kernel(const float* __restrict__ c,
                           const float* __restrict__ ada_w,
                           const float* __restrict__ ada_b) {
    int j = blockIdx.x * blockDim.x + threadIdx.x;
    if (j >= BB * ADA6) return;
    int b = j / ADA6, col = j % ADA6;
    float acc = ada_b[col];
    #pragma unroll 8
    for (int k = 0; k < COND; k++)
        acc += c[b * COND + k] * ada_w[k * ADA6 + col];
    g_ada[j] = acc;
}

// ---------------- LayerNorm + adaLN modulation (bf16 out) ----------------
__global__ void ln_mod_kernel(const float* __restrict__ src, bf16* __restrict__ dst,
                              const float* __restrict__ lnw,
                              int shift_ofs, int scale_ofs) {
    int row = blockIdx.x;
    int b = row / SEQ;
    const float* xr = src + (size_t)row * DIM;
    float s = 0.f, s2 = 0.f;
    for (int i = threadIdx.x; i < DIM; i += blockDim.x) {
        float v = xr[i];
        s += v; s2 += v * v;
    }
    #pragma unroll
    for (int o = 16; o; o >>= 1) {
        s  += __shfl_xor_sync(0xffffffffu, s,  o);
        s2 += __shfl_xor_sync(0xffffffffu, s2, o);
    }
    __shared__ float red[64];
    int wid = threadIdx.x >> 5, lid = threadIdx.x & 31;
    if (lid == 0) { red[wid] = s; red[32 + wid] = s2; }
    __syncthreads();
    if (threadIdx.x == 0) {
        float a = 0.f, bs = 0.f;
        int nw = blockDim.x >> 5;
        for (int w = 0; w < nw; w++) { a += red[w]; bs += red[32 + w]; }
        red[0] = a; red[32] = bs;
    }
    __syncthreads();
    float mu  = red[0] * (1.0f / DIM);
    float var = red[32] * (1.0f / DIM) - mu * mu;
    float inv = rsqrtf(var + 1e-5f);
    const float* ada = g_ada + b * ADA6;
    for (int i = threadIdx.x; i < DIM; i += blockDim.x) {
        float v = (xr[i] - mu) * inv * lnw[i];
        dst[(size_t)row * DIM + i] =
            __float2bfloat16(v * (1.f + ada[scale_ofs + i]) + ada[shift_ofs + i]);
    }
}

// ---------------- bf16 tensor-core GEMM, cp.async double-buffered ----------------
// C[M,N] = A[M,K](bf16,row) @ B[K,N](bf16,row). Tiles 128x128x32, 256 thr, 8 warps 4x2.
// mode 0: fp32 out | 1: gate*acc+res (fp32) | 2: gelu(acc+bias) -> bf16 | 3: gate*(acc+bias)+res (fp32)
#define AST 40   // A smem row stride (bf16 elems) = 80B, conflict-free for ldmatrix

__device__ __forceinline__ unsigned sptr(const void* p) {
    return (unsigned)__cvta_generic_to_shared(p);
}
__device__ __forceinline__ void cpa16(unsigned dst, const void* src) {
    asm volatile("cp.async.cg.shared.global [%0], [%1], 16;" :: "r"(dst), "l"(src));
}
__device__ __forceinline__ void ldsm4(unsigned* r, unsigned addr) {
    asm volatile("ldmatrix.sync.aligned.m8n8.x4.shared.b16 {%0,%1,%2,%3}, [%4];"
                 : "=r"(r[0]), "=r"(r[1]), "=r"(r[2]), "=r"(r[3]) : "r"(addr));
}
__device__ __forceinline__ void ldsm4t(unsigned* r, unsigned addr) {
    asm volatile("ldmatrix.sync.aligned.m8n8.x4.trans.shared.b16 {%0,%1,%2,%3}, [%4];"
                 : "=r"(r[0]), "=r"(r[1]), "=r"(r[2]), "=r"(r[3]) : "r"(addr));
}
__device__ __forceinline__ void mma_bf16(float* c, const unsigned* a, const unsigned* b) {
    asm volatile(
        "mma.sync.aligned.m16n8k16.row.col.f32.bf16.bf16.f32 "
        "{%0,%1,%2,%3}, {%4,%5,%6,%7}, {%8,%9}, {%0,%1,%2,%3};"
        : "+f"(c[0]), "+f"(c[1]), "+f"(c[2]), "+f"(c[3])
        : "r"(a[0]), "r"(a[1]), "r"(a[2]), "r"(a[3]), "r"(b[0]), "r"(b[1]));
}

__global__ void __launch_bounds__(256)
gemm_bf16(const bf16* __restrict__ A, const bf16* __restrict__ Bm,
          void* __restrict__ Cv, int N, int K, int mode,
          const float* __restrict__ bias,
          const float* __restrict__ res, int gate_ofs) {
    __shared__ bf16 As[2][128 * AST];
    __shared__ bf16 Bs[2][32 * 128];
    int tid = threadIdx.x;
    int lane = tid & 31, warp = tid >> 5;
    int warpm = warp >> 1, warpn = warp & 1;
    int g = lane >> 2, tg = lane & 3;
    int m0 = blockIdx.y * 128, n0 = blockIdx.x * 128;

    float acc[2][8][4] = {};

    // cp.async index precompute
    int am = tid >> 2;                 // A: thread -> (m, chunk); 2 per thread
    int ac = tid & 3;
    int bk = tid >> 4;                 // B: (k, chunk)
    int bc = tid & 15;

    int T = K / 32;
    // prologue: stage 0
    {
        #pragma unroll
        for (int i = 0; i < 2; i++) {
            int m = am + i * 64;
            cpa16(sptr(&As[0][m * AST + ac * 8]), &A[(size_t)(m0 + m) * K + ac * 8]);
            int k = bk + i * 16;
            cpa16(sptr(&Bs[0][k * 128 + ((bc ^ (k & 7)) * 8)]),
                  &Bm[(size_t)k * N + n0 + bc * 8]);
        }
        asm volatile("cp.async.commit_group;");
    }

    for (int it = 0; it < T; it++) {
        int buf = it & 1;
        if (it + 1 < T) {
            int k0 = (it + 1) * 32;
            #pragma unroll
            for (int i = 0; i < 2; i++) {
                int m = am + i * 64;
                cpa16(sptr(&As[buf ^ 1][m * AST + ac * 8]),
                      &A[(size_t)(m0 + m) * K + k0 + ac * 8]);
                int k = bk + i * 16;
                cpa16(sptr(&Bs[buf ^ 1][k * 128 + ((bc ^ (k & 7)) * 8)]),
                      &Bm[(size_t)(k0 + k) * N + n0 + bc * 8]);
            }
            asm volatile("cp.async.commit_group;");
            asm volatile("cp.async.wait_group 1;");
        } else {
            asm volatile("cp.async.wait_group 0;");
        }
        __syncthreads();

        #pragma unroll
        for (int s = 0; s < 2; s++) {
            unsigned a[2][4], b[8][2];
            #pragma unroll
            for (int mt = 0; mt < 2; mt++) {
                int row = warpm * 32 + mt * 16 + (lane & 15);
                unsigned addr = sptr(&As[buf][row * AST + s * 16 + (lane >> 4) * 8]);
                ldsm4(a[mt], addr);
            }
            #pragma unroll
            for (int p = 0; p < 4; p++) {
                int k = s * 16 + (lane & 7) + ((lane >> 3) & 1) * 8;
                int nn = warpn * 64 + p * 16 + (lane >> 4) * 8;
                unsigned addr = sptr(&Bs[buf][k * 128 + (((nn >> 3) ^ (k & 7)) * 8)]);
                unsigned r[4];
                ldsm4t(r, addr);
                b[2 * p][0] = r[0]; b[2 * p][1] = r[1];
                b[2 * p + 1][0] = r[2]; b[2 * p + 1][1] = r[3];
            }
            #pragma unroll
            for (int mt = 0; mt < 2; mt++)
                #pragma unroll
                for (int nt = 0; nt < 8; nt++)
                    mma_bf16(acc[mt][nt], a[mt], b[nt]);
        }
        __syncthreads();
    }

    // epilogue
    float* C = (float*)Cv;
    bf16* Cb = (bf16*)Cv;
    #pragma unroll
    for (int mt = 0; mt < 2; mt++) {
        #pragma unroll
        for (int i = 0; i < 2; i++) {
            int row = m0 + warpm * 32 + mt * 16 + g + i * 8;
            int bidx = row >> 11;
            #pragma unroll
            for (int nt = 0; nt < 8; nt++) {
                int col = n0 + warpn * 64 + nt * 8 + 2 * tg;
                float v0 = acc[mt][nt][i * 2 + 0];
                float v1 = acc[mt][nt][i * 2 + 1];
                if (mode == 1) {
                    float g0 = g_ada[bidx * ADA6 + gate_ofs + col];
                    float g1 = g_ada[bidx * ADA6 + gate_ofs + col + 1];
                    v0 = g0 * v0 + res[(size_t)row * N + col];
                    v1 = g1 * v1 + res[(size_t)row * N + col + 1];
                } else if (mode == 2) {
                    v0 += bias[col]; v1 += bias[col + 1];
                    float t0 = v0 * v0 * v0, t1 = v1 * v1 * v1;
                    v0 = 0.5f * v0 * (1.f + tanhf(0.7978845608028654f * (v0 + 0.044715f * t0)));
                    v1 = 0.5f * v1 * (1.f + tanhf(0.7978845608028654f * (v1 + 0.044715f * t1)));
                    __nv_bfloat162 pk = __floats2bfloat162_rn(v0, v1);
                    *(__nv_bfloat162*)&Cb[(size_t)row * N + col] = pk;
                    continue;
                } else if (mode == 3) {
                    v0 += bias[col]; v1 += bias[col + 1];
                    float g0 = g_ada[bidx * ADA6 + gate_ofs + col];
                    float g1 = g_ada[bidx * ADA6 + gate_ofs + col + 1];
                    v0 = g0 * v0 + res[(size_t)row * N + col];
                    v1 = g1 * v1 + res[(size_t)row * N + col + 1];
                }
                *(float2*)&C[(size_t)row * N + col] = make_float2(v0, v1);
            }
        }
    }
}

// ---------------- RoPE on q, k, v (fp32 qkv) ----------------
__global__ void rope_kernel(const float* __restrict__ cosb, const float* __restrict__ sinb) {
    int idx = blockIdx.x * blockDim.x + threadIdx.x;
    const int total = BB * SEQ * 3 * HEADS * 32;
    if (idx >= total) return;
    int d = idx & 31;
    int h = (idx >> 5) % HEADS;
    int t = (idx / (32 * HEADS)) % 3;
    int pos = (idx / (32 * HEADS * 3)) % SEQ;
    int b = idx / (32 * HEADS * 3 * SEQ);
    int ph = pos & (NHALF - 1);
    float c1 = cosb[ph * HD + d],      s1 = sinb[ph * HD + d];
    float c2 = cosb[ph * HD + d + 32], s2 = sinb[ph * HD + d + 32];
    float* base = g_qkv + ((size_t)(b * SEQ + pos) * 3 + t) * DIM + h * HD;
    float v1 = base[d], v2 = base[d + 32];
    base[d]      = v1 * c1 - v2 * s1;
    base[d + 32] = v2 * c2 + v1 * s2;
}

// ---------------- Block-sparse attention (online softmax), bf16 output ----------------
__global__ void attn_kernel() {
    int qb = blockIdx.x;
    int h  = blockIdx.y;
    int b  = blockIdx.z;
    __shared__ float Ks[16][64];
    __shared__ float Vs[16][64];
    int tid = threadIdx.x;
    int w = tid >> 5, lane = tid & 31;
    int qpos = qb * 16 + w;
    size_t qbase = ((size_t)(b * SEQ + qpos) * 3) * DIM + h * HD;
    float qa  = g_qkv[qbase + lane];
    float qbv = g_qkv[qbase + lane + 32];
    int bl = qb & 63;
    bool second = qb >= 64;
    int niter = bl + 1;
    float m = -1e30f, l = 0.f, a0 = 0.f, a1 = 0.f;
    for (int it = 0; it < niter; it++) {
        int kb = second ? (64 + it) : (it == 0 ? qb : 64 + (it - 1));
        for (int r = tid; r < 1024; r += 512) {
            int row = r >> 6, d = r & 63;
            int kpos = kb * 16 + row;
            size_t kbase = ((size_t)(b * SEQ + kpos) * 3 + 1) * DIM + h * HD + d;
            Ks[row][d] = g_qkv[kbase];
            Vs[row][d] = g_qkv[kbase + DIM];
        }
        __syncthreads();
        float sloc[16];
        #pragma unroll
        for (int j = 0; j < 16; j++) {
            float p = qa * Ks[j][lane] + qbv * Ks[j][lane + 32];
            #pragma unroll
            for (int o = 16; o; o >>= 1) p += __shfl_xor_sync(0xffffffffu, p, o);
            sloc[j] = p * 0.125f;
        }
        float bm = sloc[0];
        #pragma unroll
        for (int j = 1; j < 16; j++) bm = fmaxf(bm, sloc[j]);
        float nm = fmaxf(m, bm);
        float corr = __expf(m - nm);
        l *= corr; a0 *= corr; a1 *= corr;
        #pragma unroll
        for (int j = 0; j < 16; j++) {
            float p = __expf(sloc[j] - nm);
            l += p;
            a0 += p * Vs[j][lane];
            a1 += p * Vs[j][lane + 32];
        }
        m = nm;
        __syncthreads();
    }
    float invl = 1.f / l;
    size_t obase = (size_t)(b * SEQ + qpos) * DIM + h * HD;
    g_o[obase + lane]      = __float2bfloat16(a0 * invl);
    g_o[obase + lane + 32] = __float2bfloat16(a1 * invl);
}

// ---------------- launch ----------------
extern "C" void kernel_launch(void* const* d_in, const int* in_sizes, int n_in,
                              void* d_out, int out_size) {
    const float* x     = (const float*)d_in[0];
    const float* cosb  = (const float*)d_in[1];
    const float* sinb  = (const float*)d_in[2];
    const float* c     = (const float*)d_in[3];
    const float* W_qkv = (const float*)d_in[4];
    const float* W_out = (const float*)d_in[5];
    const float* ln1_w = (const float*)d_in[6];
    const float* ln2_w = (const float*)d_in[7];
    const float* w1    = (const float*)d_in[8];
    const float* b1    = (const float*)d_in[9];
    const float* w2    = (const float*)d_in[10];
    const float* b2    = (const float*)d_in[11];
    const float* ada_w = (const float*)d_in[12];
    const float* ada_b = (const float*)d_in[13];
    float* out = (float*)d_out;

    bf16 *h, *o, *h2, *mlp, *wq, *wo, *w1b, *w2b;
    float *qkv, *x1;
    cudaGetSymbolAddress((void**)&h,   g_h);
    cudaGetSymbolAddress((void**)&qkv, g_qkv);
    cudaGetSymbolAddress((void**)&o,   g_o);
    cudaGetSymbolAddress((void**)&x1,  g_x1);
    cudaGetSymbolAddress((void**)&h2,  g_h2);
    cudaGetSymbolAddress((void**)&mlp, g_mlp);
    cudaGetSymbolAddress((void**)&wq,  g_wq);
    cudaGetSymbolAddress((void**)&wo,  g_wo);
    cudaGetSymbolAddress((void**)&w1b, g_w1);
    cudaGetSymbolAddress((void**)&w2b, g_w2);

    const int M = BB * SEQ;  // 4096

    // weight conversion (parallel, independent)
    cvt_kernel<<<1024, 256>>>(W_qkv, wq,  DIM * 3 * DIM);
    cvt_kernel<<<512,  256>>>(W_out, wo,  DIM * DIM);
    cvt_kernel<<<1024, 256>>>(w1,    w1b, DIM * DFF);
    cvt_kernel<<<1024, 256>>>(w2,    w2b, DFF * DIM);

    ada_kernel<<<(BB * ADA6 + 255) / 256, 256>>>(c, ada_w, ada_b);
    ln_mod_kernel<<<M, 256>>>(x, h, ln1_w, 0, DIM);
    // QKV GEMM -> fp32 qkv
    gemm_bf16<<<dim3(3 * DIM / 128, M / 128), 256>>>(h, wq, qkv, 3 * DIM, DIM, 0,
                                                     nullptr, nullptr, 0);
    {
        int total = BB * SEQ * 3 * HEADS * 32;
        rope_kernel<<<(total + 255) / 256, 256>>>(cosb, sinb);
    }
    attn_kernel<<<dim3(128, HEADS, BB), 512>>>();
    // out-proj + gate_msa + residual(x) -> x1 (fp32)
    gemm_bf16<<<dim3(DIM / 128, M / 128), 256>>>(o, wo, x1, DIM, DIM, 1,
                                                 nullptr, x, 2 * DIM);
    ln_mod_kernel<<<M, 256>>>(x1, h2, ln2_w, 3 * DIM, 4 * DIM);
    // MLP1 + bias + gelu -> bf16 mlp
    gemm_bf16<<<dim3(DFF / 128, M / 128), 256>>>(h2, w1b, mlp, DFF, DIM, 2,
                                                 b1, nullptr, 0);
    // MLP2 + bias + gate_mlp + residual(x1) -> out (fp32)
    gemm_bf16<<<dim3(DIM / 128, M / 128), 256>>>(mlp, w2b, out, DIM, DFF, 3,
                                                 b2, x1, 5 * DIM);
}